// round 2
// baseline (speedup 1.0000x reference)
#include <cuda_runtime.h>
#include <cstdint>
#include <math.h>

#define E_EDGES 65536
#define N_NODES_ 8192

// Scratch (static device globals are the allowed scratch mechanism)
__device__ float g_h[(size_t)E_EDGES * 128];    // radial MLP hidden (scaled)
__device__ float g_w[(size_t)E_EDGES * 4096];   // per-edge TP weights
__device__ int   g_idx64;                       // 1 if edge_index is int64

// ---------------------------------------------------------------------------
// helpers
// ---------------------------------------------------------------------------
__device__ __forceinline__ uint32_t f2tf32(float f) {
    uint32_t u;
    asm("cvt.rna.tf32.f32 %0, %1;" : "=r"(u) : "f"(f));
    return u;
}

__device__ __forceinline__ void mma_tf32(float* c, const uint32_t* a, const uint32_t* b) {
    asm volatile(
        "mma.sync.aligned.m16n8k8.row.col.f32.tf32.tf32.f32 "
        "{%0,%1,%2,%3}, {%4,%5,%6,%7}, {%8,%9}, {%0,%1,%2,%3};\n"
        : "+f"(c[0]), "+f"(c[1]), "+f"(c[2]), "+f"(c[3])
        : "r"(a[0]), "r"(a[1]), "r"(a[2]), "r"(a[3]),
          "r"(b[0]), "r"(b[1]));
}

// ---------------------------------------------------------------------------
// K_detect: classify edge_index dtype (int64 vs int32) from data pattern.
// int64 values < 8192 => every odd int32 word is 0. Sample 128 odd words.
// ---------------------------------------------------------------------------
__global__ void k_detect(const int* __restrict__ idx32) {
    const int lane = threadIdx.x;            // 32 threads
    int nz = 0;
#pragma unroll
    for (int s = 0; s < 4; s++) {
        int v = idx32[1 + 2 * (lane + 32 * s)];  // odd positions 1,3,...,255
        nz |= (v != 0);
    }
    nz = __any_sync(0xFFFFFFFFu, nz);
    if (lane == 0) g_idx64 = nz ? 0 : 1;
}

// ---------------------------------------------------------------------------
// K0: zero the output
// ---------------------------------------------------------------------------
__global__ void k_zero(float* __restrict__ out, int n) {
    int i = blockIdx.x * blockDim.x + threadIdx.x;
    if (i < n) out[i] = 0.0f;
}

// ---------------------------------------------------------------------------
// K1: h = (1.679/sqrt(128)) * silu(emb @ W1 / sqrt(64))
// 64 edges / CTA, 256 threads, thread tile 4 edges x 8 cols, K=64.
// ---------------------------------------------------------------------------
__global__ __launch_bounds__(256) void k_radial(const float* __restrict__ emb,
                                                const float* __restrict__ W1) {
    __shared__ float semb[64 * 64];   // [e][k]
    const int tid = threadIdx.x;
    const int ebase = blockIdx.x * 64;

    const float4* src = (const float4*)(emb + (size_t)ebase * 64);
    float4* dst = (float4*)semb;
#pragma unroll
    for (int t = tid; t < 1024; t += 256) dst[t] = src[t];
    __syncthreads();

    const int tx = tid & 15;        // col group: cols tx*8..tx*8+7
    const int ty = tid >> 4;        // edge group: edges ty*4..ty*4+3

    float acc[4][8];
#pragma unroll
    for (int r = 0; r < 4; r++)
#pragma unroll
        for (int c = 0; c < 8; c++) acc[r][c] = 0.0f;

#pragma unroll 8
    for (int k = 0; k < 64; k++) {
        float4 b0 = __ldg((const float4*)(W1 + k * 128 + tx * 8));
        float4 b1 = __ldg((const float4*)(W1 + k * 128 + tx * 8 + 4));
        float bb[8] = {b0.x, b0.y, b0.z, b0.w, b1.x, b1.y, b1.z, b1.w};
#pragma unroll
        for (int r = 0; r < 4; r++) {
            float a = semb[(ty * 4 + r) * 64 + k];
#pragma unroll
            for (int c = 0; c < 8; c++) acc[r][c] += a * bb[c];
        }
    }

    const float OUT_SCALE = 0.14840403f;  // 1.679 / sqrt(128)
#pragma unroll
    for (int r = 0; r < 4; r++) {
        float o[8];
#pragma unroll
        for (int c = 0; c < 8; c++) {
            float z = acc[r][c] * 0.125f;            // W1 / sqrt(64)
            float sg = 1.0f / (1.0f + expf(-z));     // sigmoid
            o[c] = OUT_SCALE * z * sg;               // gain*silu, W2-scale folded
        }
        float* hp = g_h + (size_t)(ebase + ty * 4 + r) * 128 + tx * 8;
        *(float4*)hp       = make_float4(o[0], o[1], o[2], o[3]);
        *(float4*)(hp + 4) = make_float4(o[4], o[5], o[6], o[7]);
    }
}

// ---------------------------------------------------------------------------
// K2: g_w = g_h @ W2   (tf32 tensor cores)
// CTA tile 128(M) x 128(N), K=128 fully smem-resident.
// 8 warps in 2x4 grid, warp tile 64x32; m16n8k8 fragments.
// As stride 132 (pad 4) / Bs stride 136 (pad 8) -> conflict-free frag loads.
// ---------------------------------------------------------------------------
#define GEMM_SMEM_BYTES ((128 * 132 + 128 * 136) * 4)

__global__ __launch_bounds__(256) void k_gemm(const float* __restrict__ W2) {
    extern __shared__ uint32_t sm[];
    uint32_t* As = sm;                 // [128][132]
    uint32_t* Bs = sm + 128 * 132;     // [128][136]

    const int tid = threadIdx.x;
    const int nblk = blockIdx.x;       // 0..31
    const int mblk = blockIdx.y;       // 0..511

    // Load A tile (h rows are contiguous 128 floats)
    const float4* ag = (const float4*)(g_h + (size_t)mblk * 128 * 128);
#pragma unroll
    for (int t = tid; t < 4096; t += 256) {
        int r = t >> 5, c4 = (t & 31) << 2;
        float4 v = ag[t];
        uint32_t* d = &As[r * 132 + c4];
        d[0] = f2tf32(v.x); d[1] = f2tf32(v.y); d[2] = f2tf32(v.z); d[3] = f2tf32(v.w);
    }
    // Load B tile: W2[k][nblk*128 + c]
#pragma unroll
    for (int t = tid; t < 4096; t += 256) {
        int r = t >> 5, c4 = (t & 31) << 2;
        float4 v = *(const float4*)(W2 + (size_t)r * 4096 + nblk * 128 + c4);
        uint32_t* d = &Bs[r * 136 + c4];
        d[0] = f2tf32(v.x); d[1] = f2tf32(v.y); d[2] = f2tf32(v.z); d[3] = f2tf32(v.w);
    }
    __syncthreads();

    const int warp = tid >> 5, lane = tid & 31;
    const int wm = (warp >> 2) * 64;   // warp M origin
    const int wn = (warp & 3) * 32;    // warp N origin
    const int g = lane >> 2, tg = lane & 3;

    float acc[4][4][4];
#pragma unroll
    for (int mf = 0; mf < 4; mf++)
#pragma unroll
        for (int nf = 0; nf < 4; nf++)
#pragma unroll
            for (int i = 0; i < 4; i++) acc[mf][nf][i] = 0.0f;

#pragma unroll
    for (int ks = 0; ks < 16; ks++) {
        const int k0 = ks * 8;
        uint32_t af[4][4], bf[4][2];
#pragma unroll
        for (int mf = 0; mf < 4; mf++) {
            int r = wm + mf * 16;
            af[mf][0] = As[(r + g) * 132 + k0 + tg];
            af[mf][1] = As[(r + g + 8) * 132 + k0 + tg];
            af[mf][2] = As[(r + g) * 132 + k0 + tg + 4];
            af[mf][3] = As[(r + g + 8) * 132 + k0 + tg + 4];
        }
#pragma unroll
        for (int nf = 0; nf < 4; nf++) {
            int c = wn + nf * 8;
            bf[nf][0] = Bs[(k0 + tg) * 136 + c + g];
            bf[nf][1] = Bs[(k0 + tg + 4) * 136 + c + g];
        }
#pragma unroll
        for (int mf = 0; mf < 4; mf++)
#pragma unroll
            for (int nf = 0; nf < 4; nf++)
                mma_tf32(acc[mf][nf], af[mf], bf[nf]);
    }

    // Epilogue: write f32 tile to g_w
    float* cg = g_w + (size_t)(mblk * 128) * 4096 + nblk * 128;
#pragma unroll
    for (int mf = 0; mf < 4; mf++) {
#pragma unroll
        for (int nf = 0; nf < 4; nf++) {
            int r = wm + mf * 16 + g;
            int c = wn + nf * 8 + 2 * tg;
            *(float2*)&cg[(size_t)r * 4096 + c]       = make_float2(acc[mf][nf][0], acc[mf][nf][1]);
            *(float2*)&cg[(size_t)(r + 8) * 4096 + c] = make_float2(acc[mf][nf][2], acc[mf][nf][3]);
        }
    }
}

// ---------------------------------------------------------------------------
// K3: tensor product + scatter. One warp per edge; lane = w (output mul idx).
// w layout per edge: n = g*1024 + u*32 + w  (g: Wa,Wb,Wc,Wd)
// out col: [0,32) = out0[w];  32+3w+k = out1[w][k]
// ---------------------------------------------------------------------------
__global__ __launch_bounds__(256) void k_tp(const float* __restrict__ x,
                                            const void* __restrict__ eidx_raw,
                                            const float* __restrict__ eattr,
                                            float* __restrict__ out) {
    __shared__ float sA[8][6][32];
    const int warp = threadIdx.x >> 5, lane = threadIdx.x & 31;
    const int e = blockIdx.x * 8 + warp;

    long long ni, nj;
    if (g_idx64) {
        const long long* p = (const long long*)eidx_raw;
        ni = p[e];
        nj = p[E_EDGES + e];
    } else {
        const int* p = (const int*)eidx_raw;
        ni = p[e];
        nj = p[E_EDGES + e];
    }
    const float* xr = x + (size_t)ni * 128;

    const float x0  = xr[lane];
    const float x1a = xr[32 + 3 * lane];
    const float x1b = xr[33 + 3 * lane];
    const float x1c = xr[34 + 3 * lane];

    const float s0 = eattr[e * 4 + 0];
    const float s1 = eattr[e * 4 + 1];
    const float s2 = eattr[e * 4 + 2];
    const float s3 = eattr[e * 4 + 3];

    const float IS3 = 0.57735026919f;  // 1/sqrt(3)
    sA[warp][0][lane] = x0 * s0;                                  // a_a
    sA[warp][1][lane] = (x1a * s1 + x1b * s2 + x1c * s3) * IS3;   // a_b (dot)
    sA[warp][2][lane] = x0 * IS3;                                 // a_c
    const float t = s0 * IS3;
    sA[warp][3][lane] = x1a * t;                                  // a_d k=0
    sA[warp][4][lane] = x1b * t;                                  // a_d k=1
    sA[warp][5][lane] = x1c * t;                                  // a_d k=2
    __syncwarp();

    const float* wb = g_w + (size_t)e * 4096 + lane;
    float o0 = 0.f, oc = 0.f, o1x = 0.f, o1y = 0.f, o1z = 0.f;
#pragma unroll
    for (int u = 0; u < 32; u++) {
        float w0 = wb[u * 32];
        float w1 = wb[u * 32 + 1024];
        float w2 = wb[u * 32 + 2048];
        float w3 = wb[u * 32 + 3072];
        o0  += sA[warp][0][u] * w0 + sA[warp][1][u] * w1;
        oc  += sA[warp][2][u] * w2;
        o1x += sA[warp][3][u] * w3;
        o1y += sA[warp][4][u] * w3;
        o1z += sA[warp][5][u] * w3;
    }

    const float C0 = 0.04419417382f;  // NORM0 / sqrt(8)
    const float C1 = 0.07654655446f;  // NORM1 / sqrt(8)
    float* orow = out + (size_t)nj * 128;
    atomicAdd(orow + lane,            o0 * C0);
    atomicAdd(orow + 32 + 3 * lane,   (oc * s1 + o1x) * C1);
    atomicAdd(orow + 33 + 3 * lane,   (oc * s2 + o1y) * C1);
    atomicAdd(orow + 34 + 3 * lane,   (oc * s3 + o1z) * C1);
}

// ---------------------------------------------------------------------------
// launch — inputs identified by element count (order-independent):
//   x=1048576, edge_index=131072, edge_attr=262144,
//   edge_len_emb=4194304, W1=8192, W2=524288
// ---------------------------------------------------------------------------
extern "C" void kernel_launch(void* const* d_in, const int* in_sizes, int n_in,
                              void* d_out, int out_size) {
    const float* x     = nullptr;
    const void*  eidx  = nullptr;
    const float* eattr = nullptr;
    const float* emb   = nullptr;
    const float* W1    = nullptr;
    const float* W2    = nullptr;

    for (int i = 0; i < n_in; i++) {
        switch (in_sizes[i]) {
            case 1048576: x     = (const float*)d_in[i]; break;
            case 131072:  eidx  = d_in[i];               break;
            case 262144:  eattr = (const float*)d_in[i]; break;
            case 4194304: emb   = (const float*)d_in[i]; break;
            case 8192:    W1    = (const float*)d_in[i]; break;
            case 524288:  W2    = (const float*)d_in[i]; break;
            default: break;
        }
    }
    float* out = (float*)d_out;

    cudaFuncSetAttribute(k_gemm, cudaFuncAttributeMaxDynamicSharedMemorySize,
                         GEMM_SMEM_BYTES);

    k_detect<<<1, 32>>>((const int*)eidx);
    k_zero<<<(N_NODES_ * 128 + 511) / 512, 512>>>(out, N_NODES_ * 128);
    k_radial<<<E_EDGES / 64, 256>>>(emb, W1);
    k_gemm<<<dim3(32, 512), 256, GEMM_SMEM_BYTES>>>(W2);
    k_tp<<<E_EDGES / 8, 256>>>(x, eidx, eattr, out);
}

// round 5
// speedup vs baseline: 1.2237x; 1.2237x over previous
#include <cuda_runtime.h>
#include <cstdint>
#include <math.h>

#define E_EDGES 65536
#define N_NODES_ 8192

// ---------------------------------------------------------------------------
// scratch (device globals = allowed scratch)
// ---------------------------------------------------------------------------
__device__ float    g_h[(size_t)E_EDGES * 128];        // radial hidden (f32, scaled)
__device__ uint32_t g_hf[(size_t)E_EDGES * 128];       // A in tf32 fragment order
__device__ uint32_t g_w2f[(size_t)32 * 16384];         // W2 in tf32 fragment order
__device__ float    g_a[(size_t)6 * 32 * E_EDGES];     // TP coefficients [q][u][e]
__device__ int      g_idx64;

// ---------------------------------------------------------------------------
// helpers
// ---------------------------------------------------------------------------
__device__ __forceinline__ uint32_t f2tf32(float f) {
    uint32_t u;
    asm("cvt.rna.tf32.f32 %0, %1;" : "=r"(u) : "f"(f));
    return u;
}

__device__ __forceinline__ void mma_tf32(float* c, const uint32_t* a, const uint32_t* b) {
    asm volatile(
        "mma.sync.aligned.m16n8k8.row.col.f32.tf32.tf32.f32 "
        "{%0,%1,%2,%3}, {%4,%5,%6,%7}, {%8,%9}, {%0,%1,%2,%3};\n"
        : "+f"(c[0]), "+f"(c[1]), "+f"(c[2]), "+f"(c[3])
        : "r"(a[0]), "r"(a[1]), "r"(a[2]), "r"(a[3]),
          "r"(b[0]), "r"(b[1]));
}

__device__ __forceinline__ uint32_t smem_u32_of(const void* p) {
    uint32_t a;
    asm("{ .reg .u64 t; cvta.to.shared.u64 t, %1; cvt.u32.u64 %0, t; }" : "=r"(a) : "l"(p));
    return a;
}

#define CP_ASYNC16(dst, src) \
    asm volatile("cp.async.cg.shared.global [%0], [%1], 16;" :: "r"(dst), "l"(src) : "memory")
#define CP_COMMIT() asm volatile("cp.async.commit_group;" ::: "memory")
#define CP_WAIT0()  asm volatile("cp.async.wait_group 0;" ::: "memory")

// ---------------------------------------------------------------------------
// smem layout of k_fused (u32 units)
// ---------------------------------------------------------------------------
#define AF_U     0u
#define BF_U(b)  (16384u + (b) * 16384u)
#define DX_U     49152u                 // 32 x 129
#define CF_U     53280u                 // 12 x 128
#define NJ_U     54816u                 // 128
#define AT_U     54944u                 // 128 x 4
#define SMEM_U   55456u
#define SMEM_TOTAL (SMEM_U * 4u)        // 221,824 bytes

// ---------------------------------------------------------------------------
// K_detect / K_zero
// ---------------------------------------------------------------------------
__global__ void k_detect(const int* __restrict__ idx32) {
    const int lane = threadIdx.x;
    int nz = 0;
#pragma unroll
    for (int s = 0; s < 4; s++) nz |= (idx32[1 + 2 * (lane + 32 * s)] != 0);
    nz = __any_sync(0xFFFFFFFFu, nz);
    if (lane == 0) g_idx64 = nz ? 0 : 1;
}

__global__ void k_zero(float* __restrict__ out, int n) {
    int i = blockIdx.x * blockDim.x + threadIdx.x;
    if (i < n) out[i] = 0.0f;
}

// ---------------------------------------------------------------------------
// K_radial: g_h = (1.679/sqrt(128)) * silu(emb @ W1 / 8)    (f32)
// ---------------------------------------------------------------------------
__global__ __launch_bounds__(256) void k_radial(const float* __restrict__ emb,
                                                const float* __restrict__ W1) {
    __shared__ float semb[64 * 64];
    const int tid = threadIdx.x;
    const int ebase = blockIdx.x * 64;

    const float4* src = (const float4*)(emb + (size_t)ebase * 64);
    float4* dst = (float4*)semb;
    for (int t = tid; t < 1024; t += 256) dst[t] = src[t];
    __syncthreads();

    const int tx = tid & 15, ty = tid >> 4;
    float acc[4][8];
#pragma unroll
    for (int r = 0; r < 4; r++)
#pragma unroll
        for (int c = 0; c < 8; c++) acc[r][c] = 0.0f;

#pragma unroll 8
    for (int k = 0; k < 64; k++) {
        float4 b0 = __ldg((const float4*)(W1 + k * 128 + tx * 8));
        float4 b1 = __ldg((const float4*)(W1 + k * 128 + tx * 8 + 4));
        float bb[8] = {b0.x, b0.y, b0.z, b0.w, b1.x, b1.y, b1.z, b1.w};
#pragma unroll
        for (int r = 0; r < 4; r++) {
            float a = semb[(ty * 4 + r) * 64 + k];
#pragma unroll
            for (int c = 0; c < 8; c++) acc[r][c] += a * bb[c];
        }
    }

    const float OUT_SCALE = 0.14840403f;  // 1.679/sqrt(128)
#pragma unroll
    for (int r = 0; r < 4; r++) {
        float o[8];
#pragma unroll
        for (int c = 0; c < 8; c++) {
            float z = acc[r][c] * 0.125f;
            o[c] = OUT_SCALE * z / (1.0f + expf(-z));
        }
        float* hp = g_h + (size_t)(ebase + ty * 4 + r) * 128 + tx * 8;
        *(float4*)hp       = make_float4(o[0], o[1], o[2], o[3]);
        *(float4*)(hp + 4) = make_float4(o[4], o[5], o[6], o[7]);
    }
}

// ---------------------------------------------------------------------------
// K_prepa: g_h -> g_hf (tf32, HMMA a-fragment order)
// t enumerates (eblk, ks, wmi, mf, lane); writes 4 consecutive u32.
// ---------------------------------------------------------------------------
__global__ __launch_bounds__(256) void k_prepa() {
    const int t = blockIdx.x * 256 + threadIdx.x;     // 0 .. 2^21-1
    const int lane = t & 31;
    const int fr = t >> 5;
    const int mf  = fr & 3;
    const int wmi = (fr >> 2) & 1;
    const int ks  = (fr >> 3) & 15;
    const int eblk = fr >> 7;
    const int g = lane >> 2, tg = lane & 3;

    const int row = eblk * 128 + wmi * 64 + mf * 16 + g;
    const int col = ks * 8 + tg;
    const float* hb = g_h + (size_t)row * 128 + col;
    uint4 v;
    v.x = f2tf32(hb[0]);
    v.y = f2tf32(hb[8 * 128]);
    v.z = f2tf32(hb[4]);
    v.w = f2tf32(hb[8 * 128 + 4]);
    *(uint4*)(g_hf + (size_t)t * 4) = v;
}

// ---------------------------------------------------------------------------
// K_prepb: W2 -> g_w2f (tf32, HMMA b-fragment order)
// t enumerates (chunk, ks, wnq, nf, lane); writes 2 consecutive u32.
// ---------------------------------------------------------------------------
__global__ __launch_bounds__(256) void k_prepb(const float* __restrict__ W2) {
    const int t = blockIdx.x * 256 + threadIdx.x;     // 0 .. 2^18-1
    const int lane = t & 31;
    const int fr = t >> 5;
    const int nf  = fr & 3;
    const int wnq = (fr >> 2) & 3;
    const int ks  = (fr >> 4) & 15;
    const int chunk = fr >> 8;
    const int g = lane >> 2, tg = lane & 3;

    const int k0 = ks * 8 + tg;
    const int n = chunk * 128 + wnq * 32 + nf * 8 + g;
    uint2 v;
    v.x = f2tf32(W2[(size_t)k0 * 4096 + n]);
    v.y = f2tf32(W2[(size_t)(k0 + 4) * 4096 + n]);
    *(uint2*)(g_w2f + (size_t)t * 2) = v;
}

// ---------------------------------------------------------------------------
// K_coef: per-edge TP coefficients  g_a[q][u][e]
// q: 0=x0*s0 (g0), 1=dot(x1,s)*IS3 (g1), 2=x0*IS3 (g2), 3..5=x1k*s0*IS3 (g3)
// ---------------------------------------------------------------------------
__global__ __launch_bounds__(256) void k_coef(const float* __restrict__ x,
                                              const void* __restrict__ eidx_raw,
                                              const float* __restrict__ eattr) {
    const int e = blockIdx.x * 256 + threadIdx.x;
    long long ni;
    if (g_idx64) ni = ((const long long*)eidx_raw)[e];
    else         ni = ((const int*)eidx_raw)[e];

    const float* xr = x + (size_t)ni * 128;
    const float4 sv = __ldg((const float4*)(eattr + (size_t)e * 4));
    const float s0 = sv.x, s1 = sv.y, s2 = sv.z, s3 = sv.w;
    const float IS3 = 0.57735026919f;
    const float cc = s0 * IS3;

#pragma unroll 4
    for (int u = 0; u < 32; u++) {
        float x0 = xr[u];
        float xa = xr[32 + 3 * u], xb = xr[33 + 3 * u], xc = xr[34 + 3 * u];
        g_a[(size_t)(0 * 32 + u) * E_EDGES + e] = x0 * s0;
        g_a[(size_t)(1 * 32 + u) * E_EDGES + e] = (xa * s1 + xb * s2 + xc * s3) * IS3;
        g_a[(size_t)(2 * 32 + u) * E_EDGES + e] = x0 * IS3;
        g_a[(size_t)(3 * 32 + u) * E_EDGES + e] = xa * cc;
        g_a[(size_t)(4 * 32 + u) * E_EDGES + e] = xb * cc;
        g_a[(size_t)(5 * 32 + u) * E_EDGES + e] = xc * cc;
    }
}

// ---------------------------------------------------------------------------
// K_fused: per-CTA 128 edges; 32 chunks of (tf32 GEMM tile + TP reduce).
// ---------------------------------------------------------------------------
__global__ __launch_bounds__(256, 1) void k_fused(const void* __restrict__ eidx_raw,
                                                  const float* __restrict__ eattr,
                                                  float* __restrict__ out) {
    extern __shared__ uint32_t sm[];
    const uint32_t smem_base = smem_u32_of(sm);
    const int tid = threadIdx.x;
    const int warp = tid >> 5, lane = tid & 31;
    const int wmi = warp >> 2, wnq = warp & 3;
    const int g = lane >> 2, tg = lane & 3;
    const int eb = blockIdx.x * 128;

    float* DX = (float*)(sm + DX_U);
    float* CF = (float*)(sm + CF_U);
    int*   NJ = (int*)(sm + NJ_U);
    float* AT = (float*)(sm + AT_U);

    // ---- stage nj + attrs
    if (tid < 128) {
        long long nj;
        if (g_idx64) nj = ((const long long*)eidx_raw)[E_EDGES + eb + tid];
        else         nj = ((const int*)eidx_raw)[E_EDGES + eb + tid];
        NJ[tid] = (int)nj;
        const float4 sv = __ldg((const float4*)(eattr + (size_t)(eb + tid) * 4));
        AT[tid * 4 + 0] = sv.x; AT[tid * 4 + 1] = sv.y;
        AT[tid * 4 + 2] = sv.z; AT[tid * 4 + 3] = sv.w;
    }

    // ---- cp.async: A tile (64KB) + B chunk 0 (64KB)
    {
        const char* asrc = (const char*)(g_hf + (size_t)blockIdx.x * 16384);
#pragma unroll
        for (int k = 0; k < 16; k++) {
            int idx = tid + k * 256;
            CP_ASYNC16(smem_base + AF_U * 4 + idx * 16, asrc + idx * 16);
        }
        CP_COMMIT();
        const char* bsrc = (const char*)(g_w2f);
#pragma unroll
        for (int k = 0; k < 16; k++) {
            int idx = tid + k * 256;
            CP_ASYNC16(smem_base + BF_U(0) * 4 + idx * 16, bsrc + idx * 16);
        }
        CP_COMMIT();
    }
    CP_WAIT0();
    __syncthreads();

    // ---- persistent TP accumulators: [pass][4 w]
    float A0[4][4], T[4][4], Ox[4][4], Oy[4][4], Oz[4][4];
#pragma unroll
    for (int p = 0; p < 4; p++)
#pragma unroll
        for (int i = 0; i < 4; i++) { A0[p][i] = 0.f; T[p][i] = 0.f; Ox[p][i] = 0.f; Oy[p][i] = 0.f; Oz[p][i] = 0.f; }

    const int lr_t = tid >> 3;       // TP row within pass (0..31)
    const int sub  = tid & 7;        // TP w-subrange

    for (int c = 0; c < 32; ++c) {
        const int buf = c & 1;

        // prefetch next B chunk (overlaps mainloop + epilogue)
        if (c < 31) {
            const char* bsrc = (const char*)(g_w2f + (size_t)(c + 1) * 16384);
            const uint32_t bdst = smem_base + BF_U(buf ^ 1) * 4;
#pragma unroll
            for (int k = 0; k < 16; k++) {
                int idx = tid + k * 256;
                CP_ASYNC16(bdst + idx * 16, bsrc + idx * 16);
            }
            CP_COMMIT();
        }

        // ---- mainloop: D(128x128) = A @ Bchunk
        float acc[4][4][4];
#pragma unroll
        for (int mf = 0; mf < 4; mf++)
#pragma unroll
            for (int nf = 0; nf < 4; nf++)
#pragma unroll
                for (int i = 0; i < 4; i++) acc[mf][nf][i] = 0.0f;

#pragma unroll
        for (int ks = 0; ks < 16; ks++) {
            uint4 af[4];
#pragma unroll
            for (int mf = 0; mf < 4; mf++)
                af[mf] = *(const uint4*)&sm[AF_U + (((ks * 8 + wmi * 4 + mf) * 32 + lane) << 2)];
            uint2 bf[4];
#pragma unroll
            for (int nf = 0; nf < 4; nf++)
                bf[nf] = *(const uint2*)&sm[BF_U(buf) + (((ks * 16 + wnq * 4 + nf) * 32 + lane) << 1)];
#pragma unroll
            for (int mf = 0; mf < 4; mf++)
#pragma unroll
                for (int nf = 0; nf < 4; nf++)
                    mma_tf32(acc[mf][nf], (const uint32_t*)&af[mf], (const uint32_t*)&bf[nf]);
        }

        // ---- coefficient slice for this chunk
        const int gch = c >> 3;
        const int u0 = (c & 7) * 4;
        if (gch < 3) {
#pragma unroll
            for (int it = 0; it < 2; it++) {
                int idx = tid + it * 256;        // 0..511
                int du = idx >> 7, e = idx & 127;
                CF[du * 128 + e] = g_a[(size_t)(gch * 32 + u0 + du) * E_EDGES + eb + e];
            }
        } else {
#pragma unroll
            for (int it = 0; it < 6; it++) {
                int idx = tid + it * 256;        // 0..1535
                int du = idx >> 7, e = idx & 127;
                int kk = du >> 2, uu = du & 3;
                CF[du * 128 + e] = g_a[(size_t)((3 + kk) * 32 + u0 + uu) * E_EDGES + eb + e];
            }
        }

        // ---- epilogue: 4 passes of 32 rows through Dx
#pragma unroll
        for (int p = 0; p < 4; p++) {
            __syncthreads();   // Dx free (prev pass read) + CF visible (p=0)
            if (wmi == (p >> 1)) {
#pragma unroll
                for (int m = 0; m < 2; m++) {
                    const int mf = 2 * (p & 1) + m;
                    const int lr = m * 16 + g;
#pragma unroll
                    for (int nf = 0; nf < 4; nf++) {
                        const int col = wnq * 32 + nf * 8 + 2 * tg;
                        DX[lr * 129 + col]           = acc[mf][nf][0];
                        DX[lr * 129 + col + 1]       = acc[mf][nf][1];
                        DX[(lr + 8) * 129 + col]     = acc[mf][nf][2];
                        DX[(lr + 8) * 129 + col + 1] = acc[mf][nf][3];
                    }
                }
            }
            __syncthreads();
            // TP accumulate
            const int el = p * 32 + lr_t;
#pragma unroll
            for (int u = 0; u < 4; u++) {
                float dv[4];
#pragma unroll
                for (int i = 0; i < 4; i++)
                    dv[i] = DX[lr_t * 129 + u * 32 + sub * 4 + i];
                if (gch == 0 || gch == 1) {
                    float a = CF[u * 128 + el];
#pragma unroll
                    for (int i = 0; i < 4; i++) A0[p][i] += a * dv[i];
                } else if (gch == 2) {
                    float a = CF[u * 128 + el];
#pragma unroll
                    for (int i = 0; i < 4; i++) T[p][i] += a * dv[i];
                } else {
                    float ax = CF[(0 + u) * 128 + el];
                    float ay = CF[(4 + u) * 128 + el];
                    float az = CF[(8 + u) * 128 + el];
#pragma unroll
                    for (int i = 0; i < 4; i++) {
                        Ox[p][i] += ax * dv[i];
                        Oy[p][i] += ay * dv[i];
                        Oz[p][i] += az * dv[i];
                    }
                }
            }
        }
        __syncthreads();   // protect Dx/CF vs next chunk
    }

    // ---- writeout: one atomic set per edge component
    const float C0 = 0.04419417382f;   // NORM0/sqrt(8)
    const float C1 = 0.07654655446f;   // NORM1/sqrt(8)
#pragma unroll
    for (int p = 0; p < 4; p++) {
        const int el = p * 32 + lr_t;
        float* orow = out + (size_t)NJ[el] * 128;
        const float s1 = AT[el * 4 + 1], s2 = AT[el * 4 + 2], s3 = AT[el * 4 + 3];
#pragma unroll
        for (int i = 0; i < 4; i++) {
            const int w = sub * 4 + i;
            atomicAdd(orow + w, A0[p][i] * C0);
            atomicAdd(orow + 32 + 3 * w,     (T[p][i] * s1 + Ox[p][i]) * C1);
            atomicAdd(orow + 33 + 3 * w,     (T[p][i] * s2 + Oy[p][i]) * C1);
            atomicAdd(orow + 34 + 3 * w,     (T[p][i] * s3 + Oz[p][i]) * C1);
        }
    }
}

// ---------------------------------------------------------------------------
// launch — inputs bound by element count (order-independent)
// ---------------------------------------------------------------------------
extern "C" void kernel_launch(void* const* d_in, const int* in_sizes, int n_in,
                              void* d_out, int out_size) {
    const float* x = nullptr;
    const void* eidx = nullptr;
    const float* eattr = nullptr;
    const float* emb = nullptr;
    const float* W1 = nullptr;
    const float* W2 = nullptr;

    for (int i = 0; i < n_in; i++) {
        switch (in_sizes[i]) {
            case 1048576: x     = (const float*)d_in[i]; break;
            case 131072:  eidx  = d_in[i];               break;
            case 262144:  eattr = (const float*)d_in[i]; break;
            case 4194304: emb   = (const float*)d_in[i]; break;
            case 8192:    W1    = (const float*)d_in[i]; break;
            case 524288:  W2    = (const float*)d_in[i]; break;
            default: break;
        }
    }
    float* out = (float*)d_out;

    cudaFuncSetAttribute(k_fused, cudaFuncAttributeMaxDynamicSharedMemorySize, SMEM_TOTAL);

    k_detect<<<1, 32>>>((const int*)eidx);
    k_zero<<<(N_NODES_ * 128 + 511) / 512, 512>>>(out, N_NODES_ * 128);
    k_radial<<<E_EDGES / 64, 256>>>(emb, W1);
    k_prepa<<<8192, 256>>>();
    k_prepb<<<1024, 256>>>(W2);
    k_coef<<<E_EDGES / 256, 256>>>(x, eidx, eattr);
    k_fused<<<E_EDGES / 128, 256, SMEM_TOTAL>>>(eidx, eattr, out);
}

// round 7
// speedup vs baseline: 1.5140x; 1.2372x over previous
#include <cuda_runtime.h>
#include <cuda_fp16.h>
#include <cstdint>
#include <math.h>

#define E_EDGES 65536
#define N_NODES_ 8192

// ---------------------------------------------------------------------------
// scratch (device globals = allowed scratch)
// ---------------------------------------------------------------------------
__device__ float    g_h[(size_t)E_EDGES * 128];        // radial hidden (f32, scaled)
__device__ uint32_t g_hf[(size_t)E_EDGES * 64];        // A, fp16x2, m16n8k16 a-frag order
__device__ uint32_t g_w2f[(size_t)32 * 8192];          // W2, fp16x2, m16n8k16 b-frag order
__device__ float    g_a[(size_t)6 * 32 * E_EDGES];     // TP coefficients [q][u][e]
__device__ int      g_idx64;

// ---------------------------------------------------------------------------
// helpers
// ---------------------------------------------------------------------------
__device__ __forceinline__ uint32_t pack_h2(float lo, float hi) {
    __half l = __float2half_rn(lo), h = __float2half_rn(hi);
    return (uint32_t)__half_as_ushort(l) | ((uint32_t)__half_as_ushort(h) << 16);
}

__device__ __forceinline__ void mma_f16(float* c, const uint32_t* a, const uint32_t* b) {
    asm volatile(
        "mma.sync.aligned.m16n8k16.row.col.f32.f16.f16.f32 "
        "{%0,%1,%2,%3}, {%4,%5,%6,%7}, {%8,%9}, {%0,%1,%2,%3};\n"
        : "+f"(c[0]), "+f"(c[1]), "+f"(c[2]), "+f"(c[3])
        : "r"(a[0]), "r"(a[1]), "r"(a[2]), "r"(a[3]),
          "r"(b[0]), "r"(b[1]));
}

__device__ __forceinline__ uint32_t smem_u32_of(const void* p) {
    uint32_t a;
    asm("{ .reg .u64 t; cvta.to.shared.u64 t, %1; cvt.u32.u64 %0, t; }" : "=r"(a) : "l"(p));
    return a;
}

#define CP_ASYNC16(dst, src) \
    asm volatile("cp.async.cg.shared.global [%0], [%1], 16;" :: "r"(dst), "l"(src) : "memory")
#define CP_COMMIT() asm volatile("cp.async.commit_group;" ::: "memory")
#define CP_WAIT0()  asm volatile("cp.async.wait_group 0;" ::: "memory")

// ---------------------------------------------------------------------------
// smem layout of k_fused (u32 units)
// ---------------------------------------------------------------------------
#define AF_U     0u
#define BF_U(b)  (8192u + (b) * 8192u)
#define DX_U     24576u                 // 32 x 129 f32
#define CF_U     28704u                 // 12 x 128 f32
#define NJ_U     30240u                 // 128
#define AT_U     30368u                 // 128 x 4
#define SMEM_U   30880u
#define SMEM_TOTAL (SMEM_U * 4u)        // 123,520 bytes

// ---------------------------------------------------------------------------
// K_detect / K_zero
// ---------------------------------------------------------------------------
__global__ void k_detect(const int* __restrict__ idx32) {
    const int lane = threadIdx.x;
    int nz = 0;
#pragma unroll
    for (int s = 0; s < 4; s++) nz |= (idx32[1 + 2 * (lane + 32 * s)] != 0);
    nz = __any_sync(0xFFFFFFFFu, nz);
    if (lane == 0) g_idx64 = nz ? 0 : 1;
}

__global__ void k_zero(float* __restrict__ out, int n) {
    int i = blockIdx.x * blockDim.x + threadIdx.x;
    if (i < n) out[i] = 0.0f;
}

// ---------------------------------------------------------------------------
// K_radial: g_h = (1.679/sqrt(128)) * silu(emb @ W1 / 8)    (f32)
// ---------------------------------------------------------------------------
__global__ __launch_bounds__(256) void k_radial(const float* __restrict__ emb,
                                                const float* __restrict__ W1) {
    __shared__ float semb[64 * 64];
    const int tid = threadIdx.x;
    const int ebase = blockIdx.x * 64;

    const float4* src = (const float4*)(emb + (size_t)ebase * 64);
    float4* dst = (float4*)semb;
    for (int t = tid; t < 1024; t += 256) dst[t] = src[t];
    __syncthreads();

    const int tx = tid & 15, ty = tid >> 4;
    float acc[4][8];
#pragma unroll
    for (int r = 0; r < 4; r++)
#pragma unroll
        for (int c = 0; c < 8; c++) acc[r][c] = 0.0f;

#pragma unroll 8
    for (int k = 0; k < 64; k++) {
        float4 b0 = __ldg((const float4*)(W1 + k * 128 + tx * 8));
        float4 b1 = __ldg((const float4*)(W1 + k * 128 + tx * 8 + 4));
        float bb[8] = {b0.x, b0.y, b0.z, b0.w, b1.x, b1.y, b1.z, b1.w};
#pragma unroll
        for (int r = 0; r < 4; r++) {
            float a = semb[(ty * 4 + r) * 64 + k];
#pragma unroll
            for (int c = 0; c < 8; c++) acc[r][c] += a * bb[c];
        }
    }

    const float OUT_SCALE = 0.14840403f;  // 1.679/sqrt(128)
#pragma unroll
    for (int r = 0; r < 4; r++) {
        float o[8];
#pragma unroll
        for (int c = 0; c < 8; c++) {
            float z = acc[r][c] * 0.125f;
            o[c] = OUT_SCALE * z / (1.0f + expf(-z));
        }
        float* hp = g_h + (size_t)(ebase + ty * 4 + r) * 128 + tx * 8;
        *(float4*)hp       = make_float4(o[0], o[1], o[2], o[3]);
        *(float4*)(hp + 4) = make_float4(o[4], o[5], o[6], o[7]);
    }
}

// ---------------------------------------------------------------------------
// K_prepa: g_h -> g_hf (fp16x2, m16n8k16 a-fragment order)
// one thread = one uint4 = one lane's a-fragment of one (eblk, ks, wmi, mf)
// ---------------------------------------------------------------------------
__global__ __launch_bounds__(256) void k_prepa() {
    const int t = blockIdx.x * 256 + threadIdx.x;   // 0 .. 2^20-1
    const int lane = t & 31;
    const int fr = t >> 5;
    const int mf  = fr & 3;
    const int wmi = (fr >> 2) & 1;
    const int ks  = (fr >> 3) & 7;
    const int eblk = fr >> 6;
    const int g = lane >> 2, tg = lane & 3;

    const int row = eblk * 128 + wmi * 64 + mf * 16 + g;
    const int k0 = ks * 16 + 2 * tg;
    const float* r0 = g_h + (size_t)row * 128;
    const float* r8 = r0 + 8 * 128;
    uint4 v;
    v.x = pack_h2(r0[k0],     r0[k0 + 1]);
    v.y = pack_h2(r8[k0],     r8[k0 + 1]);
    v.z = pack_h2(r0[k0 + 8], r0[k0 + 9]);
    v.w = pack_h2(r8[k0 + 8], r8[k0 + 9]);
    *(uint4*)(g_hf + (size_t)t * 4) = v;
}

// ---------------------------------------------------------------------------
// K_prepb: W2 [128 k][4096 n] f32 -> g_w2f (fp16x2, m16n8k16 b-frag order)
// one thread = one uint2 = one lane's b-fragment of one (chunk, ks, wnq, nf)
// ---------------------------------------------------------------------------
__global__ __launch_bounds__(256) void k_prepb(const float* __restrict__ W2) {
    const int t = blockIdx.x * 256 + threadIdx.x;   // 0 .. 2^17-1
    const int lane = t & 31;
    const int fr = t >> 5;
    const int nf  = fr & 3;
    const int wnq = (fr >> 2) & 3;
    const int ks  = (fr >> 4) & 7;
    const int chunk = fr >> 7;
    const int g = lane >> 2, tg = lane & 3;

    const int k0 = ks * 16 + 2 * tg;
    const int n = chunk * 128 + wnq * 32 + nf * 8 + g;
    uint2 v;
    v.x = pack_h2(W2[(size_t)k0 * 4096 + n],       W2[(size_t)(k0 + 1) * 4096 + n]);
    v.y = pack_h2(W2[(size_t)(k0 + 8) * 4096 + n], W2[(size_t)(k0 + 9) * 4096 + n]);
    *(uint2*)(g_w2f + (size_t)t * 2) = v;
}

// ---------------------------------------------------------------------------
// K_coef: per-edge TP coefficients  g_a[q][u][e]
// ---------------------------------------------------------------------------
__global__ __launch_bounds__(256) void k_coef(const float* __restrict__ x,
                                              const void* __restrict__ eidx_raw,
                                              const float* __restrict__ eattr) {
    const int e = blockIdx.x * 256 + threadIdx.x;
    long long ni;
    if (g_idx64) ni = ((const long long*)eidx_raw)[e];
    else         ni = ((const int*)eidx_raw)[e];

    const float* xr = x + (size_t)ni * 128;
    const float4 sv = __ldg((const float4*)(eattr + (size_t)e * 4));
    const float s0 = sv.x, s1 = sv.y, s2 = sv.z, s3 = sv.w;
    const float IS3 = 0.57735026919f;
    const float cc = s0 * IS3;

#pragma unroll 4
    for (int u = 0; u < 32; u++) {
        float x0 = xr[u];
        float xa = xr[32 + 3 * u], xb = xr[33 + 3 * u], xc = xr[34 + 3 * u];
        g_a[(size_t)(0 * 32 + u) * E_EDGES + e] = x0 * s0;
        g_a[(size_t)(1 * 32 + u) * E_EDGES + e] = (xa * s1 + xb * s2 + xc * s3) * IS3;
        g_a[(size_t)(2 * 32 + u) * E_EDGES + e] = x0 * IS3;
        g_a[(size_t)(3 * 32 + u) * E_EDGES + e] = xa * cc;
        g_a[(size_t)(4 * 32 + u) * E_EDGES + e] = xb * cc;
        g_a[(size_t)(5 * 32 + u) * E_EDGES + e] = xc * cc;
    }
}

// ---------------------------------------------------------------------------
// K_fused: per-CTA 128 edges; 32 chunks of (fp16 GEMM tile + TP reduce).
// 8 warps, warp grid 2(M)x4(N), warp tile 64x32, m16n8k16, 8 ksteps.
// ---------------------------------------------------------------------------
__global__ __launch_bounds__(256, 1) void k_fused(const void* __restrict__ eidx_raw,
                                                  const float* __restrict__ eattr,
                                                  float* __restrict__ out) {
    extern __shared__ uint32_t sm[];
    const uint32_t smem_base = smem_u32_of(sm);
    const int tid = threadIdx.x;
    const int warp = tid >> 5, lane = tid & 31;
    const int wmi = warp >> 2, wnq = warp & 3;
    const int g = lane >> 2, tg = lane & 3;
    const int eb = blockIdx.x * 128;

    float* DX = (float*)(sm + DX_U);
    float* CF = (float*)(sm + CF_U);
    int*   NJ = (int*)(sm + NJ_U);
    float* AT = (float*)(sm + AT_U);

    // ---- stage nj + attrs
    if (tid < 128) {
        long long nj;
        if (g_idx64) nj = ((const long long*)eidx_raw)[E_EDGES + eb + tid];
        else         nj = ((const int*)eidx_raw)[E_EDGES + eb + tid];
        NJ[tid] = (int)nj;
        const float4 sv = __ldg((const float4*)(eattr + (size_t)(eb + tid) * 4));
        AT[tid * 4 + 0] = sv.x; AT[tid * 4 + 1] = sv.y;
        AT[tid * 4 + 2] = sv.z; AT[tid * 4 + 3] = sv.w;
    }

    // ---- cp.async: A tile (32KB) + B chunk 0 (32KB)
    {
        const char* asrc = (const char*)(g_hf + (size_t)blockIdx.x * 8192);
#pragma unroll
        for (int k = 0; k < 8; k++) {
            int idx = tid + k * 256;
            CP_ASYNC16(smem_base + AF_U * 4 + idx * 16, asrc + idx * 16);
        }
        const char* bsrc = (const char*)(g_w2f);
#pragma unroll
        for (int k = 0; k < 8; k++) {
            int idx = tid + k * 256;
            CP_ASYNC16(smem_base + BF_U(0) * 4 + idx * 16, bsrc + idx * 16);
        }
        CP_COMMIT();
    }

    // ---- persistent TP accumulators: [pass][4 w]
    float A0[4][4], T[4][4], Ox[4][4], Oy[4][4], Oz[4][4];
#pragma unroll
    for (int p = 0; p < 4; p++)
#pragma unroll
        for (int i = 0; i < 4; i++) { A0[p][i] = 0.f; T[p][i] = 0.f; Ox[p][i] = 0.f; Oy[p][i] = 0.f; Oz[p][i] = 0.f; }

    const int lr_t = tid >> 3;       // TP row within pass (0..31)
    const int sub  = tid & 7;        // TP w-subrange

    for (int c = 0; c < 32; ++c) {
        const int buf = c & 1;

        // chunk c data resident (issued last iteration / preloop)
        CP_WAIT0();
        __syncthreads();

        // prefetch next B chunk into the other buffer (overlaps everything below)
        if (c < 31) {
            const char* bsrc = (const char*)(g_w2f + (size_t)(c + 1) * 8192);
            const uint32_t bdst = smem_base + BF_U(buf ^ 1) * 4;
#pragma unroll
            for (int k = 0; k < 8; k++) {
                int idx = tid + k * 256;
                CP_ASYNC16(bdst + idx * 16, bsrc + idx * 16);
            }
            CP_COMMIT();
        }

        // ---- mainloop: D(128x128) = A @ Bchunk   (fp16 m16n8k16, 8 ksteps)
        float acc[4][4][4];
#pragma unroll
        for (int mf = 0; mf < 4; mf++)
#pragma unroll
            for (int nf = 0; nf < 4; nf++)
#pragma unroll
                for (int i = 0; i < 4; i++) acc[mf][nf][i] = 0.0f;

#pragma unroll
        for (int ks = 0; ks < 8; ks++) {
            uint4 af[4];
#pragma unroll
            for (int mf = 0; mf < 4; mf++)
                af[mf] = *(const uint4*)&sm[AF_U + (((ks * 8 + wmi * 4 + mf) * 32 + lane) << 2)];
            uint2 bf[4];
#pragma unroll
            for (int nf = 0; nf < 4; nf++)
                bf[nf] = *(const uint2*)&sm[BF_U(buf) + (((ks * 16 + wnq * 4 + nf) * 32 + lane) << 1)];
#pragma unroll
            for (int mf = 0; mf < 4; mf++)
#pragma unroll
                for (int nf = 0; nf < 4; nf++)
                    mma_f16(acc[mf][nf], (const uint32_t*)&af[mf], (const uint32_t*)&bf[nf]);
        }

        // ---- coefficient slice for this chunk
        const int gch = c >> 3;
        const int u0 = (c & 7) * 4;
        if (gch < 3) {
#pragma unroll
            for (int it = 0; it < 2; it++) {
                int idx = tid + it * 256;        // 0..511
                int du = idx >> 7, e = idx & 127;
                CF[du * 128 + e] = g_a[(size_t)(gch * 32 + u0 + du) * E_EDGES + eb + e];
            }
        } else {
#pragma unroll
            for (int it = 0; it < 6; it++) {
                int idx = tid + it * 256;        // 0..1535
                int du = idx >> 7, e = idx & 127;
                int kk = du >> 2, uu = du & 3;
                CF[du * 128 + e] = g_a[(size_t)((3 + kk) * 32 + u0 + uu) * E_EDGES + eb + e];
            }
        }

        // ---- epilogue: 4 passes of 32 rows through Dx
#pragma unroll
        for (int p = 0; p < 4; p++) {
            __syncthreads();   // Dx free (prev pass read) + CF visible (p=0)
            if (wmi == (p >> 1)) {
#pragma unroll
                for (int m = 0; m < 2; m++) {
                    const int mf = 2 * (p & 1) + m;
                    const int lr = m * 16 + g;
#pragma unroll
                    for (int nf = 0; nf < 4; nf++) {
                        const int col = wnq * 32 + nf * 8 + 2 * tg;
                        DX[lr * 129 + col]           = acc[mf][nf][0];
                        DX[lr * 129 + col + 1]       = acc[mf][nf][1];
                        DX[(lr + 8) * 129 + col]     = acc[mf][nf][2];
                        DX[(lr + 8) * 129 + col + 1] = acc[mf][nf][3];
                    }
                }
            }
            __syncthreads();
            // TP accumulate
            const int el = p * 32 + lr_t;
#pragma unroll
            for (int u = 0; u < 4; u++) {
                float dv[4];
#pragma unroll
                for (int i = 0; i < 4; i++)
                    dv[i] = DX[lr_t * 129 + u * 32 + sub * 4 + i];
                if (gch == 0 || gch == 1) {
                    float a = CF[u * 128 + el];
#pragma unroll
                    for (int i = 0; i < 4; i++) A0[p][i] += a * dv[i];
                } else if (gch == 2) {
                    float a = CF[u * 128 + el];
#pragma unroll
                    for (int i = 0; i < 4; i++) T[p][i] += a * dv[i];
                } else {
                    float ax = CF[(0 + u) * 128 + el];
                    float ay = CF[(4 + u) * 128 + el];
                    float az = CF[(8 + u) * 128 + el];
#pragma unroll
                    for (int i = 0; i < 4; i++) {
                        Ox[p][i] += ax * dv[i];
                        Oy[p][i] += ay * dv[i];
                        Oz[p][i] += az * dv[i];
                    }
                }
            }
        }
        __syncthreads();   // protect Dx/CF vs next chunk
    }

    // ---- writeout: one atomic set per edge component
    const float C0 = 0.04419417382f;   // NORM0/sqrt(8)
    const float C1 = 0.07654655446f;   // NORM1/sqrt(8)
#pragma unroll
    for (int p = 0; p < 4; p++) {
        const int el = p * 32 + lr_t;
        float* orow = out + (size_t)NJ[el] * 128;
        const float s1 = AT[el * 4 + 1], s2 = AT[el * 4 + 2], s3 = AT[el * 4 + 3];
#pragma unroll
        for (int i = 0; i < 4; i++) {
            const int w = sub * 4 + i;
            atomicAdd(orow + w, A0[p][i] * C0);
            atomicAdd(orow + 32 + 3 * w, (T[p][i] * s1 + Ox[p][i]) * C1);
            atomicAdd(orow + 33 + 3 * w, (T[p][i] * s2 + Oy[p][i]) * C1);
            atomicAdd(orow + 34 + 3 * w, (T[p][i] * s3 + Oz[p][i]) * C1);
        }
    }
}

// ---------------------------------------------------------------------------
// launch — inputs bound by element count (order-independent)
// ---------------------------------------------------------------------------
extern "C" void kernel_launch(void* const* d_in, const int* in_sizes, int n_in,
                              void* d_out, int out_size) {
    const float* x = nullptr;
    const void* eidx = nullptr;
    const float* eattr = nullptr;
    const float* emb = nullptr;
    const float* W1 = nullptr;
    const float* W2 = nullptr;

    for (int i = 0; i < n_in; i++) {
        switch (in_sizes[i]) {
            case 1048576: x     = (const float*)d_in[i]; break;
            case 131072:  eidx  = d_in[i];               break;
            case 262144:  eattr = (const float*)d_in[i]; break;
            case 4194304: emb   = (const float*)d_in[i]; break;
            case 8192:    W1    = (const float*)d_in[i]; break;
            case 524288:  W2    = (const float*)d_in[i]; break;
            default: break;
        }
    }
    float* out = (float*)d_out;

    cudaFuncSetAttribute(k_fused, cudaFuncAttributeMaxDynamicSharedMemorySize, SMEM_TOTAL);

    k_detect<<<1, 32>>>((const int*)eidx);
    k_zero<<<(N_NODES_ * 128 + 511) / 512, 512>>>(out, N_NODES_ * 128);
    k_radial<<<E_EDGES / 64, 256>>>(emb, W1);
    k_prepa<<<4096, 256>>>();
    k_prepb<<<512, 256>>>(W2);
    k_coef<<<E_EDGES / 256, 256>>>(x, eidx, eattr);
    k_fused<<<E_EDGES / 128, 256, SMEM_TOTAL>>>(eidx, eattr, out);
}

// round 8
// speedup vs baseline: 1.5710x; 1.0377x over previous
#include <cuda_runtime.h>
#include <cuda_fp16.h>
#include <cstdint>
#include <math.h>

#define E_EDGES 65536
#define N_NODES_ 8192

// ---------------------------------------------------------------------------
// scratch (device globals = allowed scratch)
// ---------------------------------------------------------------------------
__device__ float    g_h[(size_t)E_EDGES * 128];        // radial hidden (f32, scaled)
__device__ uint32_t g_hf[(size_t)E_EDGES * 64];        // A, fp16x2, m16n8k16 a-frag order
__device__ uint32_t g_w2f[(size_t)32 * 8192];          // W2, fp16x2, m16n8k16 b-frag order
__device__ float    g_a[(size_t)6 * 32 * E_EDGES];     // TP coefficients [q][u][e]
__device__ int      g_idx64;

// ---------------------------------------------------------------------------
// helpers
// ---------------------------------------------------------------------------
__device__ __forceinline__ uint32_t pack_h2(float lo, float hi) {
    __half l = __float2half_rn(lo), h = __float2half_rn(hi);
    return (uint32_t)__half_as_ushort(l) | ((uint32_t)__half_as_ushort(h) << 16);
}

__device__ __forceinline__ void mma_f16(float* c, const uint32_t* a, const uint32_t* b) {
    asm volatile(
        "mma.sync.aligned.m16n8k16.row.col.f32.f16.f16.f32 "
        "{%0,%1,%2,%3}, {%4,%5,%6,%7}, {%8,%9}, {%0,%1,%2,%3};\n"
        : "+f"(c[0]), "+f"(c[1]), "+f"(c[2]), "+f"(c[3])
        : "r"(a[0]), "r"(a[1]), "r"(a[2]), "r"(a[3]),
          "r"(b[0]), "r"(b[1]));
}

__device__ __forceinline__ uint32_t smem_u32_of(const void* p) {
    uint32_t a;
    asm("{ .reg .u64 t; cvta.to.shared.u64 t, %1; cvt.u32.u64 %0, t; }" : "=r"(a) : "l"(p));
    return a;
}

#define CP_ASYNC16(dst, src) \
    asm volatile("cp.async.cg.shared.global [%0], [%1], 16;" :: "r"(dst), "l"(src) : "memory")
#define CP_COMMIT() asm volatile("cp.async.commit_group;" ::: "memory")
#define CP_WAIT0()  asm volatile("cp.async.wait_group 0;" ::: "memory")

// ---------------------------------------------------------------------------
// smem layout of k_fused (u32 units)
// ---------------------------------------------------------------------------
#define AF_U     0u
#define BF_U(b)  (8192u + (b) * 8192u)
#define SR_U     24576u                 // SR[4][32][34] f32 (4352) / DX[32][129] view (4128)
#define CF_U     28928u                 // 12 x 128 f32
#define NJ_U     30464u                 // 128
#define AT_U     30592u                 // 128 x 4
#define SMEM_U   31104u
#define SMEM_TOTAL (SMEM_U * 4u)        // 124,416 bytes

// ---------------------------------------------------------------------------
// K_detect / K_zero
// ---------------------------------------------------------------------------
__global__ void k_detect(const int* __restrict__ idx32) {
    const int lane = threadIdx.x;
    int nz = 0;
#pragma unroll
    for (int s = 0; s < 4; s++) nz |= (idx32[1 + 2 * (lane + 32 * s)] != 0);
    nz = __any_sync(0xFFFFFFFFu, nz);
    if (lane == 0) g_idx64 = nz ? 0 : 1;
}

__global__ void k_zero(float* __restrict__ out, int n) {
    int i = blockIdx.x * blockDim.x + threadIdx.x;
    if (i < n) out[i] = 0.0f;
}

// ---------------------------------------------------------------------------
// K_radial: g_h = (1.679/sqrt(128)) * silu(emb @ W1 / 8)    (f32)
// ---------------------------------------------------------------------------
__global__ __launch_bounds__(256) void k_radial(const float* __restrict__ emb,
                                                const float* __restrict__ W1) {
    __shared__ float semb[64 * 64];
    const int tid = threadIdx.x;
    const int ebase = blockIdx.x * 64;

    const float4* src = (const float4*)(emb + (size_t)ebase * 64);
    float4* dst = (float4*)semb;
    for (int t = tid; t < 1024; t += 256) dst[t] = src[t];
    __syncthreads();

    const int tx = tid & 15, ty = tid >> 4;
    float acc[4][8];
#pragma unroll
    for (int r = 0; r < 4; r++)
#pragma unroll
        for (int c = 0; c < 8; c++) acc[r][c] = 0.0f;

#pragma unroll 8
    for (int k = 0; k < 64; k++) {
        float4 b0 = __ldg((const float4*)(W1 + k * 128 + tx * 8));
        float4 b1 = __ldg((const float4*)(W1 + k * 128 + tx * 8 + 4));
        float bb[8] = {b0.x, b0.y, b0.z, b0.w, b1.x, b1.y, b1.z, b1.w};
#pragma unroll
        for (int r = 0; r < 4; r++) {
            float a = semb[(ty * 4 + r) * 64 + k];
#pragma unroll
            for (int c = 0; c < 8; c++) acc[r][c] += a * bb[c];
        }
    }

    const float OUT_SCALE = 0.14840403f;  // 1.679/sqrt(128)
#pragma unroll
    for (int r = 0; r < 4; r++) {
        float o[8];
#pragma unroll
        for (int c = 0; c < 8; c++) {
            float z = acc[r][c] * 0.125f;
            o[c] = OUT_SCALE * z / (1.0f + expf(-z));
        }
        float* hp = g_h + (size_t)(ebase + ty * 4 + r) * 128 + tx * 8;
        *(float4*)hp       = make_float4(o[0], o[1], o[2], o[3]);
        *(float4*)(hp + 4) = make_float4(o[4], o[5], o[6], o[7]);
    }
}

// ---------------------------------------------------------------------------
// K_prepa: g_h -> g_hf (fp16x2, m16n8k16 a-fragment order)
// ---------------------------------------------------------------------------
__global__ __launch_bounds__(256) void k_prepa() {
    const int t = blockIdx.x * 256 + threadIdx.x;   // 0 .. 2^20-1
    const int lane = t & 31;
    const int fr = t >> 5;
    const int mf  = fr & 3;
    const int wmi = (fr >> 2) & 1;
    const int ks  = (fr >> 3) & 7;
    const int eblk = fr >> 6;
    const int g = lane >> 2, tg = lane & 3;

    const int row = eblk * 128 + wmi * 64 + mf * 16 + g;
    const int k0 = ks * 16 + 2 * tg;
    const float* r0 = g_h + (size_t)row * 128;
    const float* r8 = r0 + 8 * 128;
    uint4 v;
    v.x = pack_h2(r0[k0],     r0[k0 + 1]);
    v.y = pack_h2(r8[k0],     r8[k0 + 1]);
    v.z = pack_h2(r0[k0 + 8], r0[k0 + 9]);
    v.w = pack_h2(r8[k0 + 8], r8[k0 + 9]);
    *(uint4*)(g_hf + (size_t)t * 4) = v;
}

// ---------------------------------------------------------------------------
// K_prepb: W2 -> g_w2f (fp16x2, m16n8k16 b-frag order)
// ---------------------------------------------------------------------------
__global__ __launch_bounds__(256) void k_prepb(const float* __restrict__ W2) {
    const int t = blockIdx.x * 256 + threadIdx.x;   // 0 .. 2^17-1
    const int lane = t & 31;
    const int fr = t >> 5;
    const int nf  = fr & 3;
    const int wnq = (fr >> 2) & 3;
    const int ks  = (fr >> 4) & 7;
    const int chunk = fr >> 7;
    const int g = lane >> 2, tg = lane & 3;

    const int k0 = ks * 16 + 2 * tg;
    const int n = chunk * 128 + wnq * 32 + nf * 8 + g;
    uint2 v;
    v.x = pack_h2(W2[(size_t)k0 * 4096 + n],       W2[(size_t)(k0 + 1) * 4096 + n]);
    v.y = pack_h2(W2[(size_t)(k0 + 8) * 4096 + n], W2[(size_t)(k0 + 9) * 4096 + n]);
    *(uint2*)(g_w2f + (size_t)t * 2) = v;
}

// ---------------------------------------------------------------------------
// K_coef: per-edge TP coefficients  g_a[q][u][e]
// ---------------------------------------------------------------------------
__global__ __launch_bounds__(256) void k_coef(const float* __restrict__ x,
                                              const void* __restrict__ eidx_raw,
                                              const float* __restrict__ eattr) {
    const int e = blockIdx.x * 256 + threadIdx.x;
    long long ni;
    if (g_idx64) ni = ((const long long*)eidx_raw)[e];
    else         ni = ((const int*)eidx_raw)[e];

    const float* xr = x + (size_t)ni * 128;
    const float4 sv = __ldg((const float4*)(eattr + (size_t)e * 4));
    const float s0 = sv.x, s1 = sv.y, s2 = sv.z, s3 = sv.w;
    const float IS3 = 0.57735026919f;
    const float cc = s0 * IS3;

#pragma unroll 4
    for (int u = 0; u < 32; u++) {
        float x0 = xr[u];
        float xa = xr[32 + 3 * u], xb = xr[33 + 3 * u], xc = xr[34 + 3 * u];
        g_a[(size_t)(0 * 32 + u) * E_EDGES + e] = x0 * s0;
        g_a[(size_t)(1 * 32 + u) * E_EDGES + e] = (xa * s1 + xb * s2 + xc * s3) * IS3;
        g_a[(size_t)(2 * 32 + u) * E_EDGES + e] = x0 * IS3;
        g_a[(size_t)(3 * 32 + u) * E_EDGES + e] = xa * cc;
        g_a[(size_t)(4 * 32 + u) * E_EDGES + e] = xb * cc;
        g_a[(size_t)(5 * 32 + u) * E_EDGES + e] = xc * cc;
    }
}

// ---------------------------------------------------------------------------
// K_fused: per-CTA 128 edges; 32 chunks fp16 GEMM.
// Chunks 0-23: TP reduce in MMA fragment registers (no D exchange).
// Chunks 24-31: DX smem exchange (3 coefficients per cell).
// ---------------------------------------------------------------------------
__global__ __launch_bounds__(256, 1) void k_fused(const void* __restrict__ eidx_raw,
                                                  const float* __restrict__ eattr,
                                                  float* __restrict__ out) {
    extern __shared__ uint32_t sm[];
    const uint32_t smem_base = smem_u32_of(sm);
    const int tid = threadIdx.x;
    const int warp = tid >> 5, lane = tid & 31;
    const int wmi = warp >> 2, wnq = warp & 3;
    const int g = lane >> 2, tg = lane & 3;
    const int eb = blockIdx.x * 128;

    float* SR = (float*)(sm + SR_U);   // [4][32][34] reduce buffer
    float* DX = (float*)(sm + SR_U);   // [32][129] view (O phase)
    float* CF = (float*)(sm + CF_U);
    int*   NJ = (int*)(sm + NJ_U);
    float* AT = (float*)(sm + AT_U);

    // ---- stage nj + attrs
    if (tid < 128) {
        long long nj;
        if (g_idx64) nj = ((const long long*)eidx_raw)[E_EDGES + eb + tid];
        else         nj = ((const int*)eidx_raw)[E_EDGES + eb + tid];
        NJ[tid] = (int)nj;
        const float4 sv = __ldg((const float4*)(eattr + (size_t)(eb + tid) * 4));
        AT[tid * 4 + 0] = sv.x; AT[tid * 4 + 1] = sv.y;
        AT[tid * 4 + 2] = sv.z; AT[tid * 4 + 3] = sv.w;
    }

    // ---- cp.async: A tile (32KB) + B chunk 0 (32KB)
    {
        const char* asrc = (const char*)(g_hf + (size_t)blockIdx.x * 8192);
#pragma unroll
        for (int k = 0; k < 8; k++) {
            int idx = tid + k * 256;
            CP_ASYNC16(smem_base + AF_U * 4 + idx * 16, asrc + idx * 16);
        }
        const char* bsrc = (const char*)(g_w2f);
#pragma unroll
        for (int k = 0; k < 8; k++) {
            int idx = tid + k * 256;
            CP_ASYNC16(smem_base + BF_U(0) * 4 + idx * 16, bsrc + idx * 16);
        }
        CP_COMMIT();
    }

    // register TP accumulators
    float RA[4][4][4];                        // A0 / T phases (layout == acc)
#pragma unroll
    for (int mf = 0; mf < 4; mf++)
#pragma unroll
        for (int nf = 0; nf < 4; nf++)
#pragma unroll
            for (int i = 0; i < 4; i++) RA[mf][nf][i] = 0.f;

    float Ox[4][4], Oy[4][4], Oz[4][4];       // O phase (lr_t/sub layout)
#pragma unroll
    for (int p = 0; p < 4; p++)
#pragma unroll
        for (int i = 0; i < 4; i++) { Ox[p][i] = 0.f; Oy[p][i] = 0.f; Oz[p][i] = 0.f; }

    const int lr_t = tid >> 3;       // O-phase: row within pass
    const int sub  = tid & 7;        // O-phase: w-subrange

    const float C0 = 0.04419417382f;   // NORM0/sqrt(8)
    const float C1 = 0.07654655446f;   // NORM1/sqrt(8)

    for (int c = 0; c < 32; ++c) {
        const int buf = c & 1;
        CP_WAIT0();
        __syncthreads();

        // prefetch next B chunk
        if (c < 31) {
            const char* bsrc = (const char*)(g_w2f + (size_t)(c + 1) * 8192);
            const uint32_t bdst = smem_base + BF_U(buf ^ 1) * 4;
#pragma unroll
            for (int k = 0; k < 8; k++) {
                int idx = tid + k * 256;
                CP_ASYNC16(bdst + idx * 16, bsrc + idx * 16);
            }
            CP_COMMIT();
        }

        // ---- mainloop: D(128x128) = A @ Bchunk (fp16 m16n8k16, 8 ksteps)
        float acc[4][4][4];
#pragma unroll
        for (int mf = 0; mf < 4; mf++)
#pragma unroll
            for (int nf = 0; nf < 4; nf++)
#pragma unroll
                for (int i = 0; i < 4; i++) acc[mf][nf][i] = 0.0f;

#pragma unroll
        for (int ks = 0; ks < 8; ks++) {
            uint4 af[4];
#pragma unroll
            for (int mf = 0; mf < 4; mf++)
                af[mf] = *(const uint4*)&sm[AF_U + (((ks * 8 + wmi * 4 + mf) * 32 + lane) << 2)];
            uint2 bf[4];
#pragma unroll
            for (int nf = 0; nf < 4; nf++)
                bf[nf] = *(const uint2*)&sm[BF_U(buf) + (((ks * 16 + wnq * 4 + nf) * 32 + lane) << 1)];
#pragma unroll
            for (int mf = 0; mf < 4; mf++)
#pragma unroll
                for (int nf = 0; nf < 4; nf++)
                    mma_f16(acc[mf][nf], (const uint32_t*)&af[mf], (const uint32_t*)&bf[nf]);
        }

        const int gch = c >> 3;
        if (gch < 3) {
            // ---- register TP epilogue: this warp's cols = u = u0 + wnq
            const int u = (c & 7) * 4 + wnq;
            const float* ap = g_a + (size_t)(gch * 32 + u) * E_EDGES + eb + wmi * 64 + g;
            float c0[4], c1[4];
#pragma unroll
            for (int mf = 0; mf < 4; mf++) {
                c0[mf] = __ldg(ap + mf * 16);
                c1[mf] = __ldg(ap + mf * 16 + 8);
            }
#pragma unroll
            for (int mf = 0; mf < 4; mf++)
#pragma unroll
                for (int nf = 0; nf < 4; nf++) {
                    RA[mf][nf][0] += c0[mf] * acc[mf][nf][0];
                    RA[mf][nf][1] += c0[mf] * acc[mf][nf][1];
                    RA[mf][nf][2] += c1[mf] * acc[mf][nf][2];
                    RA[mf][nf][3] += c1[mf] * acc[mf][nf][3];
                }

            // ---- phase-end reductions
            if (c == 15 || c == 23) {
                const int isT = (c == 23);
#pragma unroll 1
                for (int round = 0; round < 4; round++) {
                    const int rwmi = round >> 1, rhalf = round & 1;
                    __syncthreads();
                    if (wmi == rwmi) {
#pragma unroll
                        for (int mm = 0; mm < 2; mm++) {
                            const int mf = 2 * rhalf + mm;
#pragma unroll
                            for (int nf = 0; nf < 4; nf++) {
                                const int w = nf * 8 + 2 * tg;
                                float* p0 = SR + (wnq * 32 + mm * 16 + g) * 34 + w;
                                float* p8 = p0 + 8 * 34;
                                *(float2*)p0 = make_float2(RA[mf][nf][0], RA[mf][nf][1]);
                                *(float2*)p8 = make_float2(RA[mf][nf][2], RA[mf][nf][3]);
                            }
                        }
                    }
                    __syncthreads();
#pragma unroll
                    for (int k = 0; k < 4; k++) {
                        const int cell = tid + k * 256;      // 0..1023
                        const int row = cell >> 5, w = cell & 31;
                        float s = SR[(0 * 32 + row) * 34 + w] + SR[(1 * 32 + row) * 34 + w]
                                + SR[(2 * 32 + row) * 34 + w] + SR[(3 * 32 + row) * 34 + w];
                        const int e = rwmi * 64 + rhalf * 32 + row;
                        float* orow = out + (size_t)NJ[e] * 128;
                        if (!isT) {
                            atomicAdd(orow + w, s * C0);
                        } else {
                            const float sc = s * C1;
                            atomicAdd(orow + 32 + 3 * w, sc * AT[e * 4 + 1]);
                            atomicAdd(orow + 33 + 3 * w, sc * AT[e * 4 + 2]);
                            atomicAdd(orow + 34 + 3 * w, sc * AT[e * 4 + 3]);
                        }
                    }
                }
                if (!isT) {   // zero RA for T phase
#pragma unroll
                    for (int mf = 0; mf < 4; mf++)
#pragma unroll
                        for (int nf = 0; nf < 4; nf++)
#pragma unroll
                            for (int i = 0; i < 4; i++) RA[mf][nf][i] = 0.f;
                }
            }
        } else {
            // ---- O phase: CF staging + DX exchange (R7 path, gch==3 only)
            const int u0 = (c & 7) * 4;
#pragma unroll
            for (int it = 0; it < 6; it++) {
                int idx = tid + it * 256;        // 0..1535
                int du = idx >> 7, e = idx & 127;
                int kk = du >> 2, uu = du & 3;
                CF[du * 128 + e] = g_a[(size_t)((3 + kk) * 32 + u0 + uu) * E_EDGES + eb + e];
            }
#pragma unroll
            for (int p = 0; p < 4; p++) {
                __syncthreads();
                if (wmi == (p >> 1)) {
#pragma unroll
                    for (int m = 0; m < 2; m++) {
                        const int mf = 2 * (p & 1) + m;
                        const int lr = m * 16 + g;
#pragma unroll
                        for (int nf = 0; nf < 4; nf++) {
                            const int col = wnq * 32 + nf * 8 + 2 * tg;
                            DX[lr * 129 + col]           = acc[mf][nf][0];
                            DX[lr * 129 + col + 1]       = acc[mf][nf][1];
                            DX[(lr + 8) * 129 + col]     = acc[mf][nf][2];
                            DX[(lr + 8) * 129 + col + 1] = acc[mf][nf][3];
                        }
                    }
                }
                __syncthreads();
                const int el = p * 32 + lr_t;
#pragma unroll
                for (int u = 0; u < 4; u++) {
                    float dv[4];
#pragma unroll
                    for (int i = 0; i < 4; i++)
                        dv[i] = DX[lr_t * 129 + u * 32 + sub * 4 + i];
                    float ax = CF[(0 + u) * 128 + el];
                    float ay = CF[(4 + u) * 128 + el];
                    float az = CF[(8 + u) * 128 + el];
#pragma unroll
                    for (int i = 0; i < 4; i++) {
                        Ox[p][i] += ax * dv[i];
                        Oy[p][i] += ay * dv[i];
                        Oz[p][i] += az * dv[i];
                    }
                }
            }
            __syncthreads();   // protect DX/CF vs next chunk
        }
    }

    // ---- final writeout: O part only (out1 components)
#pragma unroll
    for (int p = 0; p < 4; p++) {
        const int el = p * 32 + lr_t;
        float* orow = out + (size_t)NJ[el] * 128;
#pragma unroll
        for (int i = 0; i < 4; i++) {
            const int w = sub * 4 + i;
            atomicAdd(orow + 32 + 3 * w, Ox[p][i] * C1);
            atomicAdd(orow + 33 + 3 * w, Oy[p][i] * C1);
            atomicAdd(orow + 34 + 3 * w, Oz[p][i] * C1);
        }
    }
}

// ---------------------------------------------------------------------------
// launch — inputs bound by element count (order-independent)
// ---------------------------------------------------------------------------
extern "C" void kernel_launch(void* const* d_in, const int* in_sizes, int n_in,
                              void* d_out, int out_size) {
    const float* x = nullptr;
    const void* eidx = nullptr;
    const float* eattr = nullptr;
    const float* emb = nullptr;
    const float* W1 = nullptr;
    const float* W2 = nullptr;

    for (int i = 0; i < n_in; i++) {
        switch (in_sizes[i]) {
            case 1048576: x     = (const float*)d_in[i]; break;
            case 131072:  eidx  = d_in[i];               break;
            case 262144:  eattr = (const float*)d_in[i]; break;
            case 4194304: emb   = (const float*)d_in[i]; break;
            case 8192:    W1    = (const float*)d_in[i]; break;
            case 524288:  W2    = (const float*)d_in[i]; break;
            default: break;
        }
    }
    float* out = (float*)d_out;

    cudaFuncSetAttribute(k_fused, cudaFuncAttributeMaxDynamicSharedMemorySize, SMEM_TOTAL);

    k_detect<<<1, 32>>>((const int*)eidx);
    k_zero<<<(N_NODES_ * 128 + 511) / 512, 512>>>(out, N_NODES_ * 128);
    k_radial<<<E_EDGES / 64, 256>>>(emb, W1);
    k_prepa<<<4096, 256>>>();
    k_prepb<<<512, 256>>>(W2);
    k_coef<<<E_EDGES / 256, 256>>>(x, eidx, eattr);
    k_fused<<<E_EDGES / 128, 256, SMEM_TOTAL>>>(eidx, eattr, out);
}

// round 9
// speedup vs baseline: 1.6781x; 1.0682x over previous
#include <cuda_runtime.h>
#include <cuda_fp16.h>
#include <cstdint>
#include <math.h>

#define E_EDGES 65536
#define N_NODES_ 8192

// ---------------------------------------------------------------------------
// scratch (device globals = allowed scratch)
// ---------------------------------------------------------------------------
__device__ uint32_t g_hf[(size_t)E_EDGES * 64];        // A, fp16x2, m16n8k16 a-frag order
__device__ uint32_t g_w2f[(size_t)32 * 8192];          // W2, fp16x2, m16n8k16 b-frag order
__device__ float    g_a[(size_t)6 * 32 * E_EDGES];     // TP coefficients [q][u][e]
__device__ int      g_idx64;

// ---------------------------------------------------------------------------
// helpers
// ---------------------------------------------------------------------------
__device__ __forceinline__ uint32_t pack_h2(float lo, float hi) {
    __half l = __float2half_rn(lo), h = __float2half_rn(hi);
    return (uint32_t)__half_as_ushort(l) | ((uint32_t)__half_as_ushort(h) << 16);
}

__device__ __forceinline__ void mma_f16(float* c, const uint32_t* a, const uint32_t* b) {
    asm volatile(
        "mma.sync.aligned.m16n8k16.row.col.f32.f16.f16.f32 "
        "{%0,%1,%2,%3}, {%4,%5,%6,%7}, {%8,%9}, {%0,%1,%2,%3};\n"
        : "+f"(c[0]), "+f"(c[1]), "+f"(c[2]), "+f"(c[3])
        : "r"(a[0]), "r"(a[1]), "r"(a[2]), "r"(a[3]),
          "r"(b[0]), "r"(b[1]));
}

__device__ __forceinline__ uint32_t smem_u32_of(const void* p) {
    uint32_t a;
    asm("{ .reg .u64 t; cvta.to.shared.u64 t, %1; cvt.u32.u64 %0, t; }" : "=r"(a) : "l"(p));
    return a;
}

#define CP_ASYNC16(dst, src) \
    asm volatile("cp.async.cg.shared.global [%0], [%1], 16;" :: "r"(dst), "l"(src) : "memory")
#define CP_COMMIT() asm volatile("cp.async.commit_group;" ::: "memory")
#define CP_WAIT0()  asm volatile("cp.async.wait_group 0;" ::: "memory")

// ---------------------------------------------------------------------------
// smem layout of k_fused (u32 units)
// ---------------------------------------------------------------------------
#define AF_U     0u
#define BF_U(b)  (8192u + (b) * 8192u)
#define SR_U     24576u                 // SR[4][32][34] f32 / DX[32][129] view
#define CF_U     28928u                 // 12 x 128 f32
#define NJ_U     30464u                 // 128
#define AT_U     30592u                 // 128 x 4
#define SMEM_U   31104u
#define SMEM_TOTAL (SMEM_U * 4u)        // 124,416 bytes

// ---------------------------------------------------------------------------
// K_detect / K_zero
// ---------------------------------------------------------------------------
__global__ void k_detect(const int* __restrict__ idx32) {
    const int lane = threadIdx.x;
    int nz = 0;
#pragma unroll
    for (int s = 0; s < 4; s++) nz |= (idx32[1 + 2 * (lane + 32 * s)] != 0);
    nz = __any_sync(0xFFFFFFFFu, nz);
    if (lane == 0) g_idx64 = nz ? 0 : 1;
}

__global__ void k_zero(float* __restrict__ out, int n) {
    int i = blockIdx.x * blockDim.x + threadIdx.x;
    if (i < n) out[i] = 0.0f;
}

// ---------------------------------------------------------------------------
// K_radial: h = (1.679/sqrt128)*silu(emb @ W1/8), emitted DIRECTLY as fp16
// m16n8k16 a-fragments into g_hf (no f32 g_h roundtrip, no prep kernel).
// CTA = 64 edges = one wmi-half of a 128-edge block.
// ---------------------------------------------------------------------------
#define SO_STRIDE 130
__global__ __launch_bounds__(256) void k_radial(const float* __restrict__ emb,
                                                const float* __restrict__ W1) {
    __shared__ float sbuf[64 * SO_STRIDE];   // 33,280 B; aliases semb then s_o
    float* semb = sbuf;                       // [64][64] input staging
    const int tid = threadIdx.x;
    const int ebase = blockIdx.x * 64;

    const float4* src = (const float4*)(emb + (size_t)ebase * 64);
    for (int t = tid; t < 1024; t += 256) ((float4*)semb)[t] = src[t];
    __syncthreads();

    const int tx = tid & 15, ty = tid >> 4;
    float acc[4][8];
#pragma unroll
    for (int r = 0; r < 4; r++)
#pragma unroll
        for (int c = 0; c < 8; c++) acc[r][c] = 0.0f;

#pragma unroll 8
    for (int k = 0; k < 64; k++) {
        float4 b0 = __ldg((const float4*)(W1 + k * 128 + tx * 8));
        float4 b1 = __ldg((const float4*)(W1 + k * 128 + tx * 8 + 4));
        float bb[8] = {b0.x, b0.y, b0.z, b0.w, b1.x, b1.y, b1.z, b1.w};
#pragma unroll
        for (int r = 0; r < 4; r++) {
            float a = semb[(ty * 4 + r) * 64 + k];
#pragma unroll
            for (int c = 0; c < 8; c++) acc[r][c] += a * bb[c];
        }
    }

    // silu in registers
    const float OUT_SCALE = 0.14840403f;  // 1.679/sqrt(128)
#pragma unroll
    for (int r = 0; r < 4; r++)
#pragma unroll
        for (int c = 0; c < 8; c++) {
            float z = acc[r][c] * 0.125f;
            acc[r][c] = OUT_SCALE * z / (1.0f + expf(-z));
        }

    __syncthreads();   // all semb reads done; reuse sbuf as s_o[64][SO_STRIDE]
    float* s_o = sbuf;
#pragma unroll
    for (int r = 0; r < 4; r++) {
        float* row = s_o + (ty * 4 + r) * SO_STRIDE + tx * 8;
#pragma unroll
        for (int c = 0; c < 8; c++) row[c] = acc[r][c];
    }
    __syncthreads();

    // fragment emission: 1024 units = (ks, mf, lane); 4 per thread
    const int eblk = ebase >> 7, wmi = (ebase >> 6) & 1;
#pragma unroll
    for (int k = 0; k < 4; k++) {
        const int unit = tid + k * 256;
        const int lane = unit & 31;
        const int mf = (unit >> 5) & 3;
        const int ks = unit >> 7;
        const int g = lane >> 2, tg = lane & 3;
        const int row = mf * 16 + g;
        const int col = ks * 16 + 2 * tg;
        const float* r0 = s_o + row * SO_STRIDE;
        const float* r8 = r0 + 8 * SO_STRIDE;
        uint4 v;
        v.x = pack_h2(r0[col],     r0[col + 1]);
        v.y = pack_h2(r8[col],     r8[col + 1]);
        v.z = pack_h2(r0[col + 8], r0[col + 9]);
        v.w = pack_h2(r8[col + 8], r8[col + 9]);
        const int fr = eblk * 64 + ks * 8 + wmi * 4 + mf;
        *(uint4*)(g_hf + ((size_t)fr * 32 + lane) * 4) = v;
    }
}

// ---------------------------------------------------------------------------
// K_prepb: W2 -> g_w2f (fp16x2, m16n8k16 b-frag order)
// ---------------------------------------------------------------------------
__global__ __launch_bounds__(256) void k_prepb(const float* __restrict__ W2) {
    const int t = blockIdx.x * 256 + threadIdx.x;   // 0 .. 2^17-1
    const int lane = t & 31;
    const int fr = t >> 5;
    const int nf  = fr & 3;
    const int wnq = (fr >> 2) & 3;
    const int ks  = (fr >> 4) & 7;
    const int chunk = fr >> 7;
    const int g = lane >> 2, tg = lane & 3;

    const int k0 = ks * 16 + 2 * tg;
    const int n = chunk * 128 + wnq * 32 + nf * 8 + g;
    uint2 v;
    v.x = pack_h2(W2[(size_t)k0 * 4096 + n],       W2[(size_t)(k0 + 1) * 4096 + n]);
    v.y = pack_h2(W2[(size_t)(k0 + 8) * 4096 + n], W2[(size_t)(k0 + 9) * 4096 + n]);
    *(uint2*)(g_w2f + (size_t)t * 2) = v;
}

// ---------------------------------------------------------------------------
// K_coef: per-edge TP coefficients  g_a[q][u][e]
// ---------------------------------------------------------------------------
__global__ __launch_bounds__(256) void k_coef(const float* __restrict__ x,
                                              const void* __restrict__ eidx_raw,
                                              const float* __restrict__ eattr) {
    const int e = blockIdx.x * 256 + threadIdx.x;
    long long ni;
    if (g_idx64) ni = ((const long long*)eidx_raw)[e];
    else         ni = ((const int*)eidx_raw)[e];

    const float* xr = x + (size_t)ni * 128;
    const float4 sv = __ldg((const float4*)(eattr + (size_t)e * 4));
    const float s0 = sv.x, s1 = sv.y, s2 = sv.z, s3 = sv.w;
    const float IS3 = 0.57735026919f;
    const float cc = s0 * IS3;

#pragma unroll 4
    for (int u = 0; u < 32; u++) {
        float x0 = xr[u];
        float xa = xr[32 + 3 * u], xb = xr[33 + 3 * u], xc = xr[34 + 3 * u];
        g_a[(size_t)(0 * 32 + u) * E_EDGES + e] = x0 * s0;
        g_a[(size_t)(1 * 32 + u) * E_EDGES + e] = (xa * s1 + xb * s2 + xc * s3) * IS3;
        g_a[(size_t)(2 * 32 + u) * E_EDGES + e] = x0 * IS3;
        g_a[(size_t)(3 * 32 + u) * E_EDGES + e] = xa * cc;
        g_a[(size_t)(4 * 32 + u) * E_EDGES + e] = xb * cc;
        g_a[(size_t)(5 * 32 + u) * E_EDGES + e] = xc * cc;
    }
}

// ---------------------------------------------------------------------------
// K_fused: 1024 CTAs = (eblk 0..511) x (nhalf 0..1); 16 chunks each.
//   nhalf=0: chunks 0-15  (out0 phase; SR reduction + atomics at c==15)
//   nhalf=1: chunks 16-31 (T phase -> reduce at c==23; O phase 24-31 via DX)
// ---------------------------------------------------------------------------
__global__ __launch_bounds__(256, 1) void k_fused(const void* __restrict__ eidx_raw,
                                                  const float* __restrict__ eattr,
                                                  float* __restrict__ out) {
    extern __shared__ uint32_t sm[];
    const uint32_t smem_base = smem_u32_of(sm);
    const int tid = threadIdx.x;
    const int warp = tid >> 5, lane = tid & 31;
    const int wmi = warp >> 2, wnq = warp & 3;
    const int g = lane >> 2, tg = lane & 3;
    const int eblk = blockIdx.x >> 1, nhalf = blockIdx.x & 1;
    const int eb = eblk * 128;
    const int cbase = nhalf * 16;

    float* SR = (float*)(sm + SR_U);
    float* DX = (float*)(sm + SR_U);
    float* CF = (float*)(sm + CF_U);
    int*   NJ = (int*)(sm + NJ_U);
    float* AT = (float*)(sm + AT_U);

    // ---- stage nj + attrs
    if (tid < 128) {
        long long nj;
        if (g_idx64) nj = ((const long long*)eidx_raw)[E_EDGES + eb + tid];
        else         nj = ((const int*)eidx_raw)[E_EDGES + eb + tid];
        NJ[tid] = (int)nj;
        const float4 sv = __ldg((const float4*)(eattr + (size_t)(eb + tid) * 4));
        AT[tid * 4 + 0] = sv.x; AT[tid * 4 + 1] = sv.y;
        AT[tid * 4 + 2] = sv.z; AT[tid * 4 + 3] = sv.w;
    }

    // ---- cp.async: A tile (32KB) + first B chunk (32KB)
    {
        const char* asrc = (const char*)(g_hf + (size_t)eblk * 8192);
#pragma unroll
        for (int k = 0; k < 8; k++) {
            int idx = tid + k * 256;
            CP_ASYNC16(smem_base + AF_U * 4 + idx * 16, asrc + idx * 16);
        }
        const char* bsrc = (const char*)(g_w2f + (size_t)cbase * 8192);
#pragma unroll
        for (int k = 0; k < 8; k++) {
            int idx = tid + k * 256;
            CP_ASYNC16(smem_base + BF_U(0) * 4 + idx * 16, bsrc + idx * 16);
        }
        CP_COMMIT();
    }

    float RA[4][4][4];
#pragma unroll
    for (int mf = 0; mf < 4; mf++)
#pragma unroll
        for (int nf = 0; nf < 4; nf++)
#pragma unroll
            for (int i = 0; i < 4; i++) RA[mf][nf][i] = 0.f;

    float Ox[4][4], Oy[4][4], Oz[4][4];
#pragma unroll
    for (int p = 0; p < 4; p++)
#pragma unroll
        for (int i = 0; i < 4; i++) { Ox[p][i] = 0.f; Oy[p][i] = 0.f; Oz[p][i] = 0.f; }

    const int lr_t = tid >> 3;
    const int sub  = tid & 7;

    const float C0 = 0.04419417382f;   // NORM0/sqrt(8)
    const float C1 = 0.07654655446f;   // NORM1/sqrt(8)

    for (int cc = 0; cc < 16; ++cc) {
        const int c = cbase + cc;
        const int buf = cc & 1;
        CP_WAIT0();
        __syncthreads();

        // prefetch next B chunk
        if (cc < 15) {
            const char* bsrc = (const char*)(g_w2f + (size_t)(c + 1) * 8192);
            const uint32_t bdst = smem_base + BF_U(buf ^ 1) * 4;
#pragma unroll
            for (int k = 0; k < 8; k++) {
                int idx = tid + k * 256;
                CP_ASYNC16(bdst + idx * 16, bsrc + idx * 16);
            }
            CP_COMMIT();
        }

        // ---- mainloop: D(128x128) = A @ Bchunk (fp16 m16n8k16, 8 ksteps)
        float acc[4][4][4];
#pragma unroll
        for (int mf = 0; mf < 4; mf++)
#pragma unroll
            for (int nf = 0; nf < 4; nf++)
#pragma unroll
                for (int i = 0; i < 4; i++) acc[mf][nf][i] = 0.0f;

#pragma unroll
        for (int ks = 0; ks < 8; ks++) {
            uint4 af[4];
#pragma unroll
            for (int mf = 0; mf < 4; mf++)
                af[mf] = *(const uint4*)&sm[AF_U + (((ks * 8 + wmi * 4 + mf) * 32 + lane) << 2)];
            uint2 bf[4];
#pragma unroll
            for (int nf = 0; nf < 4; nf++)
                bf[nf] = *(const uint2*)&sm[BF_U(buf) + (((ks * 16 + wnq * 4 + nf) * 32 + lane) << 1)];
#pragma unroll
            for (int mf = 0; mf < 4; mf++)
#pragma unroll
                for (int nf = 0; nf < 4; nf++)
                    mma_f16(acc[mf][nf], (const uint32_t*)&af[mf], (const uint32_t*)&bf[nf]);
        }

        const int gch = c >> 3;
        if (gch < 3) {
            // ---- register TP epilogue: warp's cols = u = u0 + wnq
            const int u = (c & 7) * 4 + wnq;
            const float* ap = g_a + (size_t)(gch * 32 + u) * E_EDGES + eb + wmi * 64 + g;
            float c0[4], c1[4];
#pragma unroll
            for (int mf = 0; mf < 4; mf++) {
                c0[mf] = __ldg(ap + mf * 16);
                c1[mf] = __ldg(ap + mf * 16 + 8);
            }
#pragma unroll
            for (int mf = 0; mf < 4; mf++)
#pragma unroll
                for (int nf = 0; nf < 4; nf++) {
                    RA[mf][nf][0] += c0[mf] * acc[mf][nf][0];
                    RA[mf][nf][1] += c0[mf] * acc[mf][nf][1];
                    RA[mf][nf][2] += c1[mf] * acc[mf][nf][2];
                    RA[mf][nf][3] += c1[mf] * acc[mf][nf][3];
                }

            // ---- phase-end reductions (c==15: out0; c==23: T)
            if (c == 15 || c == 23) {
                const int isT = (c == 23);
#pragma unroll 1
                for (int round = 0; round < 4; round++) {
                    const int rwmi = round >> 1, rhalf = round & 1;
                    __syncthreads();
                    if (wmi == rwmi) {
#pragma unroll
                        for (int mm = 0; mm < 2; mm++) {
                            const int mf = 2 * rhalf + mm;
#pragma unroll
                            for (int nf = 0; nf < 4; nf++) {
                                const int w = nf * 8 + 2 * tg;
                                float* p0 = SR + (wnq * 32 + mm * 16 + g) * 34 + w;
                                float* p8 = p0 + 8 * 34;
                                *(float2*)p0 = make_float2(RA[mf][nf][0], RA[mf][nf][1]);
                                *(float2*)p8 = make_float2(RA[mf][nf][2], RA[mf][nf][3]);
                            }
                        }
                    }
                    __syncthreads();
#pragma unroll
                    for (int k = 0; k < 4; k++) {
                        const int cell = tid + k * 256;
                        const int row = cell >> 5, w = cell & 31;
                        float s = SR[(0 * 32 + row) * 34 + w] + SR[(1 * 32 + row) * 34 + w]
                                + SR[(2 * 32 + row) * 34 + w] + SR[(3 * 32 + row) * 34 + w];
                        const int e = rwmi * 64 + rhalf * 32 + row;
                        float* orow = out + (size_t)NJ[e] * 128;
                        if (!isT) {
                            atomicAdd(orow + w, s * C0);
                        } else {
                            const float sc = s * C1;
                            atomicAdd(orow + 32 + 3 * w, sc * AT[e * 4 + 1]);
                            atomicAdd(orow + 33 + 3 * w, sc * AT[e * 4 + 2]);
                            atomicAdd(orow + 34 + 3 * w, sc * AT[e * 4 + 3]);
                        }
                    }
                }
            }
        } else {
            // ---- O phase (chunks 24-31): CF staging + DX exchange
            const int u0 = (c & 7) * 4;
#pragma unroll
            for (int it = 0; it < 6; it++) {
                int idx = tid + it * 256;
                int du = idx >> 7, e = idx & 127;
                int kk = du >> 2, uu = du & 3;
                CF[du * 128 + e] = g_a[(size_t)((3 + kk) * 32 + u0 + uu) * E_EDGES + eb + e];
            }
#pragma unroll
            for (int p = 0; p < 4; p++) {
                __syncthreads();
                if (wmi == (p >> 1)) {
#pragma unroll
                    for (int m = 0; m < 2; m++) {
                        const int mf = 2 * (p & 1) + m;
                        const int lr = m * 16 + g;
#pragma unroll
                        for (int nf = 0; nf < 4; nf++) {
                            const int col = wnq * 32 + nf * 8 + 2 * tg;
                            DX[lr * 129 + col]           = acc[mf][nf][0];
                            DX[lr * 129 + col + 1]       = acc[mf][nf][1];
                            DX[(lr + 8) * 129 + col]     = acc[mf][nf][2];
                            DX[(lr + 8) * 129 + col + 1] = acc[mf][nf][3];
                        }
                    }
                }
                __syncthreads();
                const int el = p * 32 + lr_t;
#pragma unroll
                for (int u = 0; u < 4; u++) {
                    float dv[4];
#pragma unroll
                    for (int i = 0; i < 4; i++)
                        dv[i] = DX[lr_t * 129 + u * 32 + sub * 4 + i];
                    float ax = CF[(0 + u) * 128 + el];
                    float ay = CF[(4 + u) * 128 + el];
                    float az = CF[(8 + u) * 128 + el];
#pragma unroll
                    for (int i = 0; i < 4; i++) {
                        Ox[p][i] += ax * dv[i];
                        Oy[p][i] += ay * dv[i];
                        Oz[p][i] += az * dv[i];
                    }
                }
            }
            __syncthreads();
        }
    }

    // ---- final writeout: O part (nhalf==1 only)
    if (nhalf == 1) {
#pragma unroll
        for (int p = 0; p < 4; p++) {
            const int el = p * 32 + lr_t;
            float* orow = out + (size_t)NJ[el] * 128;
#pragma unroll
            for (int i = 0; i < 4; i++) {
                const int w = sub * 4 + i;
                atomicAdd(orow + 32 + 3 * w, Ox[p][i] * C1);
                atomicAdd(orow + 33 + 3 * w, Oy[p][i] * C1);
                atomicAdd(orow + 34 + 3 * w, Oz[p][i] * C1);
            }
        }
    }
}

// ---------------------------------------------------------------------------
// launch — inputs bound by element count (order-independent)
// ---------------------------------------------------------------------------
extern "C" void kernel_launch(void* const* d_in, const int* in_sizes, int n_in,
                              void* d_out, int out_size) {
    const float* x = nullptr;
    const void* eidx = nullptr;
    const float* eattr = nullptr;
    const float* emb = nullptr;
    const float* W1 = nullptr;
    const float* W2 = nullptr;

    for (int i = 0; i < n_in; i++) {
        switch (in_sizes[i]) {
            case 1048576: x     = (const float*)d_in[i]; break;
            case 131072:  eidx  = d_in[i];               break;
            case 262144:  eattr = (const float*)d_in[i]; break;
            case 4194304: emb   = (const float*)d_in[i]; break;
            case 8192:    W1    = (const float*)d_in[i]; break;
            case 524288:  W2    = (const float*)d_in[i]; break;
            default: break;
        }
    }
    float* out = (float*)d_out;

    cudaFuncSetAttribute(k_fused, cudaFuncAttributeMaxDynamicSharedMemorySize, SMEM_TOTAL);

    k_detect<<<1, 32>>>((const int*)eidx);
    k_zero<<<(N_NODES_ * 128 + 511) / 512, 512>>>(out, N_NODES_ * 128);
    k_radial<<<E_EDGES / 64, 256>>>(emb, W1);
    k_prepb<<<512, 256>>>(W2);
    k_coef<<<E_EDGES / 256, 256>>>(x, eidx, eattr);
    k_fused<<<1024, 256, SMEM_TOTAL>>>(eidx, eattr, out);
}